// round 15
// baseline (speedup 1.0000x reference)
#include <cuda_runtime.h>
#include <cuda_fp16.h>
#include <cstdint>

#define NN      50000
#define NE      800000
#define F       64
#define F4      16
#define OUTF    256
#define SCAN_B  512
#define NBLK    ((NN + SCAN_B - 1) / SCAN_B)   // 98

// -------- scratch (device globals; no allocation allowed) --------
__device__ float g_dsqrt[NN];
__device__ int   g_deg[NN];
__device__ int   g_rowptr[NN + 1];
__device__ int   g_cur[NN];
__device__ int   g_bsum[NBLK];
__device__ int   g_csrc[NE];
__device__ __half g_hxs[NN * F];                 // ping (fp16 normalized features)
__device__ __half g_hxs2[NN * F];                // pong
__device__ __half g_Xh[(size_t)NN * OUTF];       // fp16 concat (history + GEMM A operand)
__device__ __half g_Wh[OUTF * OUTF];             // W transposed: g_Wh[n*256+k] = W[k][n], fp16

// ================= init: zero_deg + W->fp16 transpose (fused) =================

__global__ void k_init(const float* __restrict__ Wm, int n) {
    int b = blockIdx.x;
    int t = threadIdx.x;
    if (b < OUTF) {
        g_Wh[(size_t)b * OUTF + t] = __float2half_rn(Wm[(size_t)t * OUTF + b]);
    } else {
        int i = (b - OUTF) * 256 + t;
        if (i < n) g_deg[i] = 0;
    }
}

__global__ void k_hist(const int* __restrict__ dst, int E) {
    int i = blockIdx.x * blockDim.x + threadIdx.x;
    if (i < E) atomicAdd(&g_deg[dst[i]], 1);
}

// ================= CSR scan =================

__global__ void k_scan1(int n) {
    __shared__ int ws[16];
    int t = threadIdx.x;
    int lane = t & 31;
    int w = t >> 5;
    int i = blockIdx.x * SCAN_B + t;
    int v = (i < n) ? g_deg[i] : 0;
    int x = v;
#pragma unroll
    for (int o = 1; o < 32; o <<= 1) {
        int y = __shfl_up_sync(0xFFFFFFFFu, x, o);
        if (lane >= o) x += y;
    }
    if (lane == 31) ws[w] = x;
    __syncthreads();
    if (w == 0) {
        int s = (lane < 16) ? ws[lane] : 0;
#pragma unroll
        for (int o = 1; o < 16; o <<= 1) {
            int y = __shfl_up_sync(0xFFFFFFFFu, s, o);
            if (lane >= o) s += y;
        }
        if (lane < 16) ws[lane] = s;
    }
    __syncthreads();
    int base = (w > 0) ? ws[w - 1] : 0;
    int incl = base + x;
    if (i < n) g_rowptr[i] = incl - v;
    if (t == SCAN_B - 1) g_bsum[blockIdx.x] = incl;
}

// Fused scan2+scan3+dsqrt, shuffle-based (3 barriers). Block = 256 threads;
// threads t<128 scan the 98 block sums; all threads hit all barriers.
__global__ void k_scan23(int n, int E) {
    __shared__ int sh[128];
    __shared__ int ws[4];
    int t = threadIdx.x;
    int lane = t & 31;
    int w = t >> 5;
    int v = (t < NBLK) ? g_bsum[t] : 0;
    if (t < 128) {
        int x = v;
#pragma unroll
        for (int o = 1; o < 32; o <<= 1) {
            int y = __shfl_up_sync(0xFFFFFFFFu, x, o);
            if (lane >= o) x += y;
        }
        if (lane == 31) ws[w] = x;
        sh[t] = x - v;   // warp-local exclusive
    }
    __syncthreads();
    if (t == 0) {
        int a = ws[0];
        int b = a + ws[1];
        int c = b + ws[2];
        ws[1] = a; ws[2] = b; ws[3] = c; ws[0] = 0;
    }
    __syncthreads();
    if (t < 128) sh[t] += ws[w];
    __syncthreads();

    int i = blockIdx.x * blockDim.x + t;
    if (i < n) {
        int r = g_rowptr[i] + sh[i / SCAN_B];
        g_rowptr[i] = r;
        g_cur[i] = r;
        int d = g_deg[i];
        if (d < 1) d = 1;
        g_dsqrt[i] = rsqrtf((float)d);
    }
    if (i == 0) g_rowptr[n] = E;
}

// ================= fp16 pack/unpack helpers =================

__device__ __forceinline__ uint2 pack_h4(float4 v) {
    __half2 h0 = __floats2half2_rn(v.x, v.y);
    __half2 h1 = __floats2half2_rn(v.z, v.w);
    uint2 u;
    u.x = *reinterpret_cast<unsigned*>(&h0);
    u.y = *reinterpret_cast<unsigned*>(&h1);
    return u;
}

__device__ __forceinline__ float4 unpack_h4(uint2 u) {
    __half2 h0 = *reinterpret_cast<__half2*>(&u.x);
    __half2 h1 = *reinterpret_cast<__half2*>(&u.y);
    float2 f0 = __half22float2(h0);
    float2 f1 = __half22float2(h1);
    return make_float4(f0.x, f0.y, f1.x, f1.y);
}

// ================= fill + prep (fused, independent outputs) =================

__global__ void k_fillprep(const int* __restrict__ src, const int* __restrict__ dst,
                           const float* __restrict__ x0, int E, int Eb, int n16) {
    int b = blockIdx.x;
    int t = threadIdx.x;
    if (b < Eb) {
        int i = b * 256 + t;
        if (i < E) {
            int pos = atomicAdd(&g_cur[dst[i]], 1);
            g_csrc[pos] = src[i];
        }
    } else {
        int i = (b - Eb) * 256 + t;
        if (i >= n16) return;
        int node = i >> 4;
        int q = i & 15;
        float ds = g_dsqrt[node];
        float4 v = reinterpret_cast<const float4*>(x0)[i];
        reinterpret_cast<uint2*>(g_Xh + (size_t)node * OUTF)[q] = pack_h4(v);
        reinterpret_cast<uint2*>(g_hxs)[i] =
            pack_h4(make_float4(v.x * ds, v.y * ds, v.z * ds, v.w * ds));
    }
}

// ================= fused SpMV + Chebyshev combine (all-fp16 memory) ============

__device__ __forceinline__ void acc_h4(float4& a, uint2 u) {
    float4 f = unpack_h4(u);
    a.x += f.x; a.y += f.y; a.z += f.z; a.w += f.w;
}

template <int STEP>
__global__ void k_spmv(const __half* __restrict__ xin, __half* __restrict__ xout,
                       const float* __restrict__ lam, int N) {
    int lane = threadIdx.x & 31;
    int gw = (blockIdx.x * blockDim.x + threadIdx.x) >> 5;
    int node = gw * 2 + (lane >> 4);
    int q = lane & 15;
    if (node >= N) return;

    int beg = g_rowptr[node];
    int end = g_rowptr[node + 1];
    float4 acc = make_float4(0.f, 0.f, 0.f, 0.f);
    int e = beg;
    for (; e + 8 <= end; e += 8) {
        uint2 u0 = reinterpret_cast<const uint2*>(xin + (size_t)g_csrc[e    ] * F)[q];
        uint2 u1 = reinterpret_cast<const uint2*>(xin + (size_t)g_csrc[e + 1] * F)[q];
        uint2 u2 = reinterpret_cast<const uint2*>(xin + (size_t)g_csrc[e + 2] * F)[q];
        uint2 u3 = reinterpret_cast<const uint2*>(xin + (size_t)g_csrc[e + 3] * F)[q];
        uint2 u4 = reinterpret_cast<const uint2*>(xin + (size_t)g_csrc[e + 4] * F)[q];
        uint2 u5 = reinterpret_cast<const uint2*>(xin + (size_t)g_csrc[e + 5] * F)[q];
        uint2 u6 = reinterpret_cast<const uint2*>(xin + (size_t)g_csrc[e + 6] * F)[q];
        uint2 u7 = reinterpret_cast<const uint2*>(xin + (size_t)g_csrc[e + 7] * F)[q];
        acc_h4(acc, u0); acc_h4(acc, u1); acc_h4(acc, u2); acc_h4(acc, u3);
        acc_h4(acc, u4); acc_h4(acc, u5); acc_h4(acc, u6); acc_h4(acc, u7);
    }
    for (; e < end; e++) {
        uint2 u = reinterpret_cast<const uint2*>(xin + (size_t)g_csrc[e] * F)[q];
        acc_h4(acc, u);
    }

    float ds = g_dsqrt[node];
    float re = 2.0f / lam[0];
    float4 out;
    if (STEP == 1) {
        float4 c = unpack_h4(reinterpret_cast<const uint2*>(g_Xh + (size_t)node * OUTF)[q]);
        float ca = -re, cc = re - 1.0f;
        out.x = ca * (acc.x * ds) + cc * c.x;
        out.y = ca * (acc.y * ds) + cc * c.y;
        out.z = ca * (acc.z * ds) + cc * c.z;
        out.w = ca * (acc.w * ds) + cc * c.w;
    } else {
        float4 c = unpack_h4(
            reinterpret_cast<const uint2*>(g_Xh + (size_t)node * OUTF + (STEP - 1) * F)[q]);
        float4 p = unpack_h4(
            reinterpret_cast<const uint2*>(g_Xh + (size_t)node * OUTF + (STEP - 2) * F)[q]);
        float ca = -2.0f * re, cc = 2.0f * (re - 1.0f);
        out.x = ca * (acc.x * ds) + cc * c.x - p.x;
        out.y = ca * (acc.y * ds) + cc * c.y - p.y;
        out.z = ca * (acc.z * ds) + cc * c.z - p.z;
        out.w = ca * (acc.w * ds) + cc * c.w - p.w;
    }
    reinterpret_cast<uint2*>(g_Xh + (size_t)node * OUTF + STEP * F)[q] = pack_h4(out);
    if (STEP < 3) {
        reinterpret_cast<uint2*>(xout + (size_t)node * F)[q] =
            pack_h4(make_float4(out.x * ds, out.y * ds, out.z * ds, out.w * ds));
    }
}

// ===== cp.async-pipelined fp16 mma GEMM (ldmatrix fragments) =====

#define BM 128
#define BN 128
#define BK2 32
#define LDH 40
#define A2_BYTES (BM * LDH * 2)
#define B2_BYTES (BN * LDH * 2)
#define STG2 (A2_BYTES + B2_BYTES)
#define GST 3
#define G_SMEM2 (STG2 * GST)

__device__ __forceinline__ void cp16(uint32_t d, const void* s, int szb) {
    asm volatile("cp.async.cg.shared.global [%0], [%1], 16, %2;"
                 :: "r"(d), "l"(s), "r"(szb));
}

__device__ __forceinline__ void g_stage2(uint32_t sb, int slot, int bm, int bn,
                                         int k0, int M, int tid) {
    uint32_t ab = sb + slot * STG2;
    uint32_t bb = ab + A2_BYTES;
#pragma unroll
    for (int t = 0; t < 4; t++) {
        int c = tid + t * 256;
        if (c < 512) {
            int row = c >> 2;
            int part = c & 3;
            int sz = (bm + row < M) ? 16 : 0;
            cp16(ab + row * (LDH * 2) + part * 16,
                 g_Xh + (size_t)(bm + row) * OUTF + k0 + part * 8, sz);
        } else {
            int c2 = c - 512;
            int nr = c2 >> 2;
            int part = c2 & 3;
            cp16(bb + nr * (LDH * 2) + part * 16,
                 g_Wh + (size_t)(bn + nr) * OUTF + k0 + part * 8, 16);
        }
    }
    asm volatile("cp.async.commit_group;" ::: "memory");
}

__device__ __forceinline__ void mma_f16(float* c, const uint32_t* a, const uint32_t* b) {
    asm volatile(
        "mma.sync.aligned.m16n8k16.row.col.f32.f16.f16.f32 "
        "{%0,%1,%2,%3}, {%4,%5,%6,%7}, {%8,%9}, {%0,%1,%2,%3};"
        : "+f"(c[0]), "+f"(c[1]), "+f"(c[2]), "+f"(c[3])
        : "r"(a[0]), "r"(a[1]), "r"(a[2]), "r"(a[3]), "r"(b[0]), "r"(b[1]));
}

__device__ __forceinline__ void ldm_x4(uint32_t& r0, uint32_t& r1, uint32_t& r2, uint32_t& r3,
                                       uint32_t addr) {
    asm volatile("ldmatrix.sync.aligned.m8n8.x4.shared.b16 {%0,%1,%2,%3}, [%4];"
                 : "=r"(r0), "=r"(r1), "=r"(r2), "=r"(r3) : "r"(addr));
}

__global__ __launch_bounds__(256, 2)
void k_gemm_h(const float* __restrict__ bias, float* __restrict__ out, int M) {
    extern __shared__ char smem[];
    uint32_t sb = (uint32_t)__cvta_generic_to_shared(smem);

    int tid = threadIdx.x;
    int lane = tid & 31;
    int wid = tid >> 5;
    int wm = wid & 1;
    int wn = wid >> 1;
    int g = lane >> 2;
    int ti = lane & 3;
    int bm = blockIdx.x * BM;
    int bn = blockIdx.y * BN;

    float acc[4][4][4];
#pragma unroll
    for (int mf = 0; mf < 4; mf++)
#pragma unroll
        for (int nf = 0; nf < 4; nf++)
#pragma unroll
            for (int r = 0; r < 4; r++) acc[mf][nf][r] = 0.f;

    g_stage2(sb, 0, bm, bn, 0, M, tid);
    g_stage2(sb, 1, bm, bn, BK2, M, tid);

    const int NT = OUTF / BK2;   // 8
#pragma unroll 1
    for (int t = 0; t < NT; t++) {
        asm volatile("cp.async.wait_group 1;" ::: "memory");
        __syncthreads();
        if (t + 2 < NT)
            g_stage2(sb, (t + 2) % GST, bm, bn, (t + 2) * BK2, M, tid);
        else
            asm volatile("cp.async.commit_group;" ::: "memory");

        int slot = t % GST;
        uint32_t abase = sb + slot * STG2;
        uint32_t bbase = abase + A2_BYTES;

#pragma unroll
        for (int ks = 0; ks < 2; ks++) {
            int ko = ks * 16;
            uint32_t af[4][4], bf[4][2];
            // A frags: lanes 0-15 -> rows (lane&15), k0; lanes 16-31 -> rows, k+8
            uint32_t a_koff = ko * 2 + ((lane & 16) ? 16 : 0);
#pragma unroll
            for (int mf = 0; mf < 4; mf++) {
                uint32_t addr = abase + (uint32_t)(wm * 64 + mf * 16 + (lane & 15)) * (LDH * 2)
                              + a_koff;
                ldm_x4(af[mf][0], af[mf][1], af[mf][2], af[mf][3], addr);
            }
            // B frags: x4 covers an nf pair (16 n-rows).
            // lanes 0-7: n0-7,k0 | 8-15: n0-7,k8 | 16-23: n8-15,k0 | 24-31: n8-15,k8
            uint32_t b_koff = ko * 2 + ((lane & 8) ? 16 : 0);
#pragma unroll
            for (int p = 0; p < 2; p++) {
                uint32_t nrow = (uint32_t)(wn * 32 + p * 16 + ((lane & 16) ? 8 : 0) + (lane & 7));
                uint32_t addr = bbase + nrow * (LDH * 2) + b_koff;
                ldm_x4(bf[2 * p][0], bf[2 * p][1], bf[2 * p + 1][0], bf[2 * p + 1][1], addr);
            }
#pragma unroll
            for (int mf = 0; mf < 4; mf++)
#pragma unroll
                for (int nf = 0; nf < 4; nf++)
                    mma_f16(acc[mf][nf], af[mf], bf[nf]);
        }
    }

#pragma unroll
    for (int mf = 0; mf < 4; mf++) {
        int row0 = bm + wm * 64 + mf * 16 + g;
#pragma unroll
        for (int nf = 0; nf < 4; nf++) {
            int col = bn + wn * 32 + nf * 8 + ti * 2;
            float2 bb = *reinterpret_cast<const float2*>(bias + col);
            if (row0 < M) {
                float2 o;
                o.x = fmaxf(acc[mf][nf][0] + bb.x, 0.f);
                o.y = fmaxf(acc[mf][nf][1] + bb.y, 0.f);
                *reinterpret_cast<float2*>(out + (size_t)row0 * OUTF + col) = o;
            }
            if (row0 + 8 < M) {
                float2 o;
                o.x = fmaxf(acc[mf][nf][2] + bb.x, 0.f);
                o.y = fmaxf(acc[mf][nf][3] + bb.y, 0.f);
                *reinterpret_cast<float2*>(out + (size_t)(row0 + 8) * OUTF + col) = o;
            }
        }
    }
}

// ================= launch =================

extern "C" void kernel_launch(void* const* d_in, const int* in_sizes, int n_in,
                              void* d_out, int out_size) {
    const float* signal = (const float*)d_in[0];
    const int*   src    = (const int*)d_in[1];
    const int*   dst    = (const int*)d_in[2];
    const float* lam    = (const float*)d_in[3];
    const float* Wm     = (const float*)d_in[4];
    const float* bias   = (const float*)d_in[5];
    float*       out    = (float*)d_out;

    int N = in_sizes[0] / F;
    int E = in_sizes[1];
    int n16 = N * F4;
    int Eb = (E + 255) / 256;
    int Pb = (n16 + 255) / 256;
    int Zb = (N + 255) / 256;

    cudaFuncSetAttribute(k_gemm_h, cudaFuncAttributeMaxDynamicSharedMemorySize, G_SMEM2);

    k_init<<<OUTF + Zb, 256>>>(Wm, N);
    k_hist<<<Eb, 256>>>(dst, E);
    k_scan1<<<NBLK, SCAN_B>>>(N);
    k_scan23<<<Zb, 256>>>(N, E);
    k_fillprep<<<Eb + Pb, 256>>>(src, dst, signal, E, Eb, n16);

    __half* xs_ping = nullptr;
    __half* xs_pong = nullptr;
    cudaGetSymbolAddress((void**)&xs_ping, g_hxs);
    cudaGetSymbolAddress((void**)&xs_pong, g_hxs2);

    int nb_spmv = (N * 16 + 255) / 256;
    k_spmv<1><<<nb_spmv, 256>>>(xs_ping, xs_pong, lam, N);
    k_spmv<2><<<nb_spmv, 256>>>(xs_pong, xs_ping, lam, N);
    k_spmv<3><<<nb_spmv, 256>>>(xs_ping, xs_pong, lam, N);

    dim3 gg((N + BM - 1) / BM, OUTF / BN);
    k_gemm_h<<<gg, 256, G_SMEM2>>>(bias, out, N);
}